// round 1
// baseline (speedup 1.0000x reference)
#include <cuda_runtime.h>
#include <cstdint>

#define N_NODES 100000
#define N_EDGES 3200000
#define IN_F    256
#define OUT_F   128
#define ROWS_PB 64

// Scratch for projected features h = x@W + b  (51.2 MB, allocation-free)
__device__ float g_h[(size_t)N_NODES * OUT_F];

// ---------------------------------------------------------------------------
// GEMM: h[row][j] = sum_k x[row][k] * W[k][j] + bias[j]
// Block: 256 threads = 8 warps. Each block computes a 64-row x 128-col tile.
// Warp w owns rows w*8..w*8+7; lane tx owns cols tx*4..tx*4+3 (float4).
// smem: xs[64][256] (64KB) + ws[256][128] (128KB) = 192KB dynamic.
// Per k-step per thread: 1 LDS.128 (W, conflict-free) + 8 LDS (x, broadcast)
// feeding 32 independent FMAs -> FMA-pipe bound.
// ---------------------------------------------------------------------------
__global__ void gemm_kernel(const float* __restrict__ x,
                            const float* __restrict__ W,
                            const float* __restrict__ bias)
{
    extern __shared__ float smem[];
    float* xs = smem;                        // [ROWS_PB][IN_F]
    float* ws = smem + ROWS_PB * IN_F;       // [IN_F][OUT_F]

    const int tid  = threadIdx.x;            // 0..255
    const int row0 = blockIdx.x * ROWS_PB;

    // Stage W (full 256x128) into smem, float4-coalesced.
    {
        const float4* W4  = reinterpret_cast<const float4*>(W);
        float4*       ws4 = reinterpret_cast<float4*>(ws);
        #pragma unroll
        for (int i = tid; i < IN_F * OUT_F / 4; i += 256)
            ws4[i] = W4[i];
    }
    // Stage x tile (guard the 32-row tail block).
    {
        const int rows = min(ROWS_PB, N_NODES - row0);
        const float4* x4  = reinterpret_cast<const float4*>(x + (size_t)row0 * IN_F);
        float4*       xs4 = reinterpret_cast<float4*>(xs);
        for (int i = tid; i < rows * IN_F / 4; i += 256)
            xs4[i] = x4[i];
    }
    __syncthreads();

    const int tx = tid & 31;   // column group (float4)
    const int wy = tid >> 5;   // warp id -> row group of 8

    const float4 b = reinterpret_cast<const float4*>(bias)[tx];
    float4 acc[8];
    #pragma unroll
    for (int r = 0; r < 8; r++) acc[r] = b;

    const float4* wsrow = reinterpret_cast<const float4*>(ws); // [IN_F][32] of float4
    const float*  xbase = xs + wy * 8 * IN_F;

    #pragma unroll 4
    for (int k = 0; k < IN_F; k++) {
        const float4 wv = wsrow[k * 32 + tx];
        #pragma unroll
        for (int r = 0; r < 8; r++) {
            const float xv = xbase[r * IN_F + k];   // warp-broadcast LDS
            acc[r].x += xv * wv.x;
            acc[r].y += xv * wv.y;
            acc[r].z += xv * wv.z;
            acc[r].w += xv * wv.w;
        }
    }

    #pragma unroll
    for (int r = 0; r < 8; r++) {
        const int row = row0 + wy * 8 + r;
        if (row < N_NODES)
            reinterpret_cast<float4*>(g_h + (size_t)row * OUT_F)[tx] = acc[r];
    }
}

// ---------------------------------------------------------------------------
// SpMM scatter: one warp per edge. Lane l handles features l*4..l*4+3.
// h[src] gather is L2-resident (51.2MB < 126MB L2). Scatter uses vectorized
// red.global.add.v4.f32 (sm_90+) -> 4x fewer atomic ops, no return trip.
// ---------------------------------------------------------------------------
__global__ void spmm_kernel(const int*   __restrict__ esrc,
                            const int*   __restrict__ edst,
                            const float* __restrict__ evals,
                            float*       __restrict__ out)
{
    const long long gt = (long long)blockIdx.x * blockDim.x + threadIdx.x;
    const long long e  = gt >> 5;
    if (e >= N_EDGES) return;
    const int lane = threadIdx.x & 31;

    const int   s = __ldg(esrc + e);   // same addr across warp -> broadcast
    const int   d = __ldg(edst + e);
    const float w = __ldg(evals + e);

    float4 v = reinterpret_cast<const float4*>(g_h + (size_t)s * OUT_F)[lane];
    v.x *= w; v.y *= w; v.z *= w; v.w *= w;

    float* addr = out + (size_t)d * OUT_F + lane * 4;   // 16B-aligned
    asm volatile("red.global.add.v4.f32 [%0], {%1,%2,%3,%4};"
                 :: "l"(addr), "f"(v.x), "f"(v.y), "f"(v.z), "f"(v.w)
                 : "memory");
}

// ---------------------------------------------------------------------------
extern "C" void kernel_launch(void* const* d_in, const int* in_sizes, int n_in,
                              void* d_out, int out_size)
{
    const float* x     = (const float*)d_in[0];
    const int*   esrc  = (const int*)  d_in[1];
    const int*   edst  = (const int*)  d_in[2];
    const float* evals = (const float*)d_in[3];
    const float* W     = (const float*)d_in[4];
    const float* bias  = (const float*)d_in[5];
    float*       out   = (float*)d_out;

    // 192KB dynamic smem for the GEMM tile (re-set every call; cheap, stateless)
    cudaFuncSetAttribute(gemm_kernel,
                         cudaFuncAttributeMaxDynamicSharedMemorySize,
                         (ROWS_PB * IN_F + IN_F * OUT_F) * sizeof(float));

    // Output must start at zero (harness poisons it).
    cudaMemsetAsync(d_out, 0, (size_t)N_NODES * OUT_F * sizeof(float), 0);

    const int gemm_blocks = (N_NODES + ROWS_PB - 1) / ROWS_PB;
    gemm_kernel<<<gemm_blocks, 256, (ROWS_PB * IN_F + IN_F * OUT_F) * sizeof(float)>>>(x, W, bias);

    const long long total_threads = (long long)N_EDGES * 32;
    const int spmm_blocks = (int)((total_threads + 255) / 256);
    spmm_kernel<<<spmm_blocks, 256>>>(esrc, edst, evals, out);
}

// round 2
// speedup vs baseline: 1.7981x; 1.7981x over previous
#include <cuda_runtime.h>
#include <cstdint>

#define N_NODES 100000
#define N_EDGES 3200000
#define IN_F    256
#define OUT_F   128

typedef unsigned long long u64;

// ---------------- device scratch (allocation-free) ----------------
__device__ float g_h[(size_t)N_NODES * OUT_F];       // 51.2 MB projected features
__device__ int   g_deg[N_NODES];                     // in-degree histogram
__device__ int   g_offs[N_NODES + 1];                // CSR row offsets (by dst)
__device__ int   g_cursor[N_NODES];                  // scatter cursors
__device__ int   g_bsum[128];                        // scan block sums
__device__ int2  g_eperm[N_EDGES];                   // permuted (src, val_bits)

// ===================================================================
// GEMM: h = x @ W + bias, fp32 via packed fma.rn.f32x2 (FFMA2).
// Block 256 thr, tile 128 rows x 128 cols, K split into 2 halves of 128.
// Thread tile: 8 rows x 8 cols held as 8x4 f32x2 accumulators.
// Per k: 4 LDS.64(w as f32x2) + 8 broadcast LDS(x) + 8 mov.b64 + 32 FFMA2.
// FFMA2 pipe-bound: 128 cyc/SM/k -> ~91us floor for 782 blocks.
// ===================================================================
__global__ void gemm_kernel(const float* __restrict__ x,
                            const float* __restrict__ W,
                            const float* __restrict__ bias)
{
    extern __shared__ float smem[];
    float* xs = smem;                 // [128 rows][128 k]
    float* ws = smem + 128 * 128;     // [128 k][128 cols]

    const int tid = threadIdx.x;
    const int tx  = tid & 15;         // col group: cols tx*8 .. tx*8+7
    const int ty  = tid >> 4;         // row group: rows ty*8 .. ty*8+7
    const int row0 = blockIdx.x * 128;

    // accumulators: 8 rows x 4 f32x2 (cols), init with bias
    u64 acc[8][4];
    {
        const u64* b64 = reinterpret_cast<const u64*>(bias) + tx * 4;
        u64 b[4];
        #pragma unroll
        for (int j = 0; j < 4; j++) b[j] = b64[j];
        #pragma unroll
        for (int r = 0; r < 8; r++)
            #pragma unroll
            for (int j = 0; j < 4; j++) acc[r][j] = b[j];
    }

    const float4* xg = reinterpret_cast<const float4*>(x);
    const float4* Wg = reinterpret_cast<const float4*>(W);
    const float4 z4 = make_float4(0.f, 0.f, 0.f, 0.f);

    #pragma unroll
    for (int h = 0; h < 2; h++) {
        if (h) __syncthreads();
        // stage x tile: rows row0..row0+127, k = h*128..h*128+127
        #pragma unroll
        for (int j = 0; j < 16; j++) {
            const int i = tid + j * 256;        // 0..4095
            const int r = i >> 5, q = i & 31;   // row-in-tile, float4-in-row
            const int grow = row0 + r;
            float4 v = (grow < N_NODES) ? xg[(size_t)grow * 64 + h * 32 + q] : z4;
            *reinterpret_cast<float4*>(&xs[r * 128 + q * 4]) = v;
        }
        // stage W half: k rows h*128..h*128+127, 128 cols
        #pragma unroll
        for (int j = 0; j < 16; j++) {
            const int i = tid + j * 256;
            const int kk = i >> 5, q = i & 31;
            *reinterpret_cast<float4*>(&ws[kk * 128 + q * 4]) =
                Wg[(size_t)(h * 128 + kk) * 32 + q];
        }
        __syncthreads();

        const float* xrow = xs + ty * 8 * 128;
        #pragma unroll 8
        for (int kk = 0; kk < 128; kk++) {
            const u64* wp = reinterpret_cast<const u64*>(ws + kk * 128 + tx * 8);
            u64 w0 = wp[0], w1 = wp[1], w2 = wp[2], w3 = wp[3];
            #pragma unroll
            for (int r = 0; r < 8; r++) {
                const float xv = xrow[r * 128 + kk];   // warp-broadcast LDS
                u64 xx;
                asm("mov.b64 %0, {%1, %1};" : "=l"(xx) : "f"(xv));
                asm("fma.rn.f32x2 %0, %1, %2, %0;" : "+l"(acc[r][0]) : "l"(xx), "l"(w0));
                asm("fma.rn.f32x2 %0, %1, %2, %0;" : "+l"(acc[r][1]) : "l"(xx), "l"(w1));
                asm("fma.rn.f32x2 %0, %1, %2, %0;" : "+l"(acc[r][2]) : "l"(xx), "l"(w2));
                asm("fma.rn.f32x2 %0, %1, %2, %0;" : "+l"(acc[r][3]) : "l"(xx), "l"(w3));
            }
        }
    }

    // epilogue: store 8 rows x 8 cols (2x STG.128 per row)
    #pragma unroll
    for (int r = 0; r < 8; r++) {
        const int grow = row0 + ty * 8 + r;
        if (grow < N_NODES) {
            u64* op = reinterpret_cast<u64*>(g_h + (size_t)grow * OUT_F + tx * 8);
            op[0] = acc[r][0]; op[1] = acc[r][1];
            op[2] = acc[r][2]; op[3] = acc[r][3];
        }
    }
}

// ===================================================================
// CSR-by-dst build: zero -> histogram -> 2-level exclusive scan -> scatter
// ===================================================================
__global__ void zero_deg_kernel()
{
    const int i = blockIdx.x * blockDim.x + threadIdx.x;
    if (i < N_NODES) g_deg[i] = 0;
}

__global__ void hist_kernel(const int* __restrict__ edst)
{
    const int e = blockIdx.x * blockDim.x + threadIdx.x;
    if (e < N_EDGES) atomicAdd(&g_deg[edst[e]], 1);   // RED.32, no return
}

// exclusive scan of g_deg within 1024-blocks, block totals to g_bsum
__global__ void scan1_kernel()
{
    __shared__ int s[1024];
    const int t   = threadIdx.x;
    const int gid = blockIdx.x * 1024 + t;
    const int v = (gid < N_NODES) ? g_deg[gid] : 0;
    s[t] = v;
    __syncthreads();
    #pragma unroll
    for (int o = 1; o < 1024; o <<= 1) {
        int a = (t >= o) ? s[t - o] : 0;
        __syncthreads();
        s[t] += a;
        __syncthreads();
    }
    if (gid < N_NODES) g_offs[gid] = s[t] - v;     // exclusive
    if (t == 1023) g_bsum[blockIdx.x] = s[t];      // block total
}

// exclusive scan of the (<=128) block totals, single block
__global__ void scan2_kernel(int nblocks)
{
    __shared__ int s[128];
    const int t = threadIdx.x;
    const int v = (t < nblocks) ? g_bsum[t] : 0;
    s[t] = v;
    __syncthreads();
    #pragma unroll
    for (int o = 1; o < 128; o <<= 1) {
        int a = (t >= o) ? s[t - o] : 0;
        __syncthreads();
        s[t] += a;
        __syncthreads();
    }
    if (t < nblocks) g_bsum[t] = s[t] - v;
}

__global__ void scan3_kernel()
{
    const int gid = blockIdx.x * blockDim.x + threadIdx.x;
    if (gid < N_NODES) {
        const int o = g_offs[gid] + g_bsum[gid >> 10];
        g_offs[gid]   = o;
        g_cursor[gid] = o;
    }
    if (gid == 0) g_offs[N_NODES] = N_EDGES;
}

__global__ void scatter_kernel(const int*   __restrict__ esrc,
                               const int*   __restrict__ edst,
                               const float* __restrict__ evals)
{
    const int e = blockIdx.x * blockDim.x + threadIdx.x;
    if (e >= N_EDGES) return;
    const int d   = edst[e];
    const int pos = atomicAdd(&g_cursor[d], 1);
    g_eperm[pos] = make_int2(esrc[e], __float_as_int(evals[e]));
}

// ===================================================================
// CSR SpMM: one warp per dst node. Lane l owns features l*4..l*4+3.
// Register accumulation, one non-atomic 512B store per node. NO atomics.
// Gather of g_h rows is L2-resident (51.2MB < 126MB).
// ===================================================================
__global__ void spmm_csr_kernel(float* __restrict__ out)
{
    const int w = (blockIdx.x * blockDim.x + threadIdx.x) >> 5;
    if (w >= N_NODES) return;
    const int lane = threadIdx.x & 31;

    const int beg = __ldg(g_offs + w);
    const int end = __ldg(g_offs + w + 1);

    float4 acc = make_float4(0.f, 0.f, 0.f, 0.f);

    int e = beg;
    // 4-way unroll: 4 independent gathers in flight per warp
    for (; e + 4 <= end; e += 4) {
        const int2 m0 = __ldg(g_eperm + e + 0);
        const int2 m1 = __ldg(g_eperm + e + 1);
        const int2 m2 = __ldg(g_eperm + e + 2);
        const int2 m3 = __ldg(g_eperm + e + 3);
        const float4 v0 = __ldg(reinterpret_cast<const float4*>(g_h + (size_t)m0.x * OUT_F) + lane);
        const float4 v1 = __ldg(reinterpret_cast<const float4*>(g_h + (size_t)m1.x * OUT_F) + lane);
        const float4 v2 = __ldg(reinterpret_cast<const float4*>(g_h + (size_t)m2.x * OUT_F) + lane);
        const float4 v3 = __ldg(reinterpret_cast<const float4*>(g_h + (size_t)m3.x * OUT_F) + lane);
        const float w0 = __int_as_float(m0.y), w1 = __int_as_float(m1.y);
        const float w2 = __int_as_float(m2.y), w3 = __int_as_float(m3.y);
        acc.x += w0 * v0.x; acc.y += w0 * v0.y; acc.z += w0 * v0.z; acc.w += w0 * v0.w;
        acc.x += w1 * v1.x; acc.y += w1 * v1.y; acc.z += w1 * v1.z; acc.w += w1 * v1.w;
        acc.x += w2 * v2.x; acc.y += w2 * v2.y; acc.z += w2 * v2.z; acc.w += w2 * v2.w;
        acc.x += w3 * v3.x; acc.y += w3 * v3.y; acc.z += w3 * v3.z; acc.w += w3 * v3.w;
    }
    for (; e < end; e++) {
        const int2 m = __ldg(g_eperm + e);
        const float4 v = __ldg(reinterpret_cast<const float4*>(g_h + (size_t)m.x * OUT_F) + lane);
        const float wv = __int_as_float(m.y);
        acc.x += wv * v.x; acc.y += wv * v.y; acc.z += wv * v.z; acc.w += wv * v.w;
    }

    reinterpret_cast<float4*>(out + (size_t)w * OUT_F)[lane] = acc;
}

// ===================================================================
extern "C" void kernel_launch(void* const* d_in, const int* in_sizes, int n_in,
                              void* d_out, int out_size)
{
    const float* x     = (const float*)d_in[0];
    const int*   esrc  = (const int*)  d_in[1];
    const int*   edst  = (const int*)  d_in[2];
    const float* evals = (const float*)d_in[3];
    const float* W     = (const float*)d_in[4];
    const float* bias  = (const float*)d_in[5];
    float*       out   = (float*)d_out;

    const int smem_gemm = 2 * 128 * 128 * (int)sizeof(float);   // 128 KB
    cudaFuncSetAttribute(gemm_kernel,
                         cudaFuncAttributeMaxDynamicSharedMemorySize, smem_gemm);

    const int scan_blocks = (N_NODES + 1023) / 1024;            // 98

    // CSR build (independent of GEMM data)
    zero_deg_kernel<<<(N_NODES + 1023) / 1024, 1024>>>();
    hist_kernel<<<(N_EDGES + 255) / 256, 256>>>(edst);
    scan1_kernel<<<scan_blocks, 1024>>>();
    scan2_kernel<<<1, 128>>>(scan_blocks);
    scan3_kernel<<<(N_NODES + 255) / 256, 256>>>();
    scatter_kernel<<<(N_EDGES + 255) / 256, 256>>>(esrc, edst, evals);

    // dense projection
    gemm_kernel<<<(N_NODES + 127) / 128, 256, smem_gemm>>>(x, W, bias);

    // atomic-free SpMM
    const int spmm_threads = 256;                                // 8 warps/block
    const int spmm_blocks  = (N_NODES * 32 + spmm_threads - 1) / spmm_threads;
    spmm_csr_kernel<<<spmm_blocks, spmm_threads>>>(out);
}

// round 3
// speedup vs baseline: 1.8647x; 1.0370x over previous
#include <cuda_runtime.h>
#include <cuda_fp16.h>
#include <cstdint>

#define N_NODES 100000
#define N_EDGES 3200000
#define IN_F    256
#define OUT_F   128

typedef unsigned long long u64;

// ---------------- device scratch (allocation-free) ----------------
__device__ __half g_h[(size_t)N_NODES * OUT_F];      // 25.6 MB projected features (fp16 storage)
__device__ int    g_deg[N_NODES];                    // in-degree histogram
__device__ int    g_offs[N_NODES + 1];               // CSR row offsets (by dst)
__device__ int    g_cursor[N_NODES];                 // scatter cursors
__device__ int    g_bsum[128];                       // scan block sums
__device__ int2   g_eperm[N_EDGES];                  // permuted (src, val_bits)

// pack one f32x2 accumulator (u64) into f16x2, memory order preserved
__device__ __forceinline__ unsigned f32x2_to_h2(u64 v)
{
    float lo, hi;
    asm("mov.b64 {%0,%1}, %2;" : "=f"(lo), "=f"(hi) : "l"(v));
    unsigned r;
    asm("cvt.rn.f16x2.f32 %0, %1, %2;" : "=r"(r) : "f"(hi), "f"(lo));
    return r;
}

// ===================================================================
// GEMM tile body: h[tile] = x[tile] @ W + bias, FFMA2 (fma.rn.f32x2).
// 256 threads, 128x128 tile, K in 2 halves of 128. 8x8 thread tile.
// Epilogue converts to fp16 -> one 16B store per row per thread.
// ===================================================================
__device__ __forceinline__ void gemm_tile(const float* __restrict__ x,
                                          const float* __restrict__ W,
                                          const float* __restrict__ bias,
                                          float* smem, int gblk)
{
    float* xs = smem;                 // [128 rows][128 k]
    float* ws = smem + 128 * 128;     // [128 k][128 cols]

    const int tid = threadIdx.x;
    const int tx  = tid & 15;         // col group: cols tx*8 .. tx*8+7
    const int ty  = tid >> 4;         // row group: rows ty*8 .. ty*8+7
    const int row0 = gblk * 128;

    u64 acc[8][4];
    {
        const u64* b64 = reinterpret_cast<const u64*>(bias) + tx * 4;
        u64 b[4];
        #pragma unroll
        for (int j = 0; j < 4; j++) b[j] = b64[j];
        #pragma unroll
        for (int r = 0; r < 8; r++)
            #pragma unroll
            for (int j = 0; j < 4; j++) acc[r][j] = b[j];
    }

    const float4* xg = reinterpret_cast<const float4*>(x);
    const float4* Wg = reinterpret_cast<const float4*>(W);
    const float4 z4 = make_float4(0.f, 0.f, 0.f, 0.f);

    #pragma unroll
    for (int h = 0; h < 2; h++) {
        if (h) __syncthreads();
        #pragma unroll
        for (int j = 0; j < 16; j++) {
            const int i = tid + j * 256;
            const int r = i >> 5, q = i & 31;
            const int grow = row0 + r;
            float4 v = (grow < N_NODES) ? xg[(size_t)grow * 64 + h * 32 + q] : z4;
            *reinterpret_cast<float4*>(&xs[r * 128 + q * 4]) = v;
        }
        #pragma unroll
        for (int j = 0; j < 16; j++) {
            const int i = tid + j * 256;
            const int kk = i >> 5, q = i & 31;
            *reinterpret_cast<float4*>(&ws[kk * 128 + q * 4]) =
                Wg[(size_t)(h * 128 + kk) * 32 + q];
        }
        __syncthreads();

        const float* xrow = xs + ty * 8 * 128;
        #pragma unroll 8
        for (int kk = 0; kk < 128; kk++) {
            const u64* wp = reinterpret_cast<const u64*>(ws + kk * 128 + tx * 8);
            u64 w0 = wp[0], w1 = wp[1], w2 = wp[2], w3 = wp[3];
            #pragma unroll
            for (int r = 0; r < 8; r++) {
                const float xv = xrow[r * 128 + kk];
                u64 xx;
                asm("mov.b64 %0, {%1, %1};" : "=l"(xx) : "f"(xv));
                asm("fma.rn.f32x2 %0, %1, %2, %0;" : "+l"(acc[r][0]) : "l"(xx), "l"(w0));
                asm("fma.rn.f32x2 %0, %1, %2, %0;" : "+l"(acc[r][1]) : "l"(xx), "l"(w1));
                asm("fma.rn.f32x2 %0, %1, %2, %0;" : "+l"(acc[r][2]) : "l"(xx), "l"(w2));
                asm("fma.rn.f32x2 %0, %1, %2, %0;" : "+l"(acc[r][3]) : "l"(xx), "l"(w3));
            }
        }
    }

    #pragma unroll
    for (int r = 0; r < 8; r++) {
        const int grow = row0 + ty * 8 + r;
        if (grow < N_NODES) {
            uint4 p;
            p.x = f32x2_to_h2(acc[r][0]);
            p.y = f32x2_to_h2(acc[r][1]);
            p.z = f32x2_to_h2(acc[r][2]);
            p.w = f32x2_to_h2(acc[r][3]);
            // 8 halves = 16 bytes at byte offset tx*16 within the 256B row
            *reinterpret_cast<uint4*>(reinterpret_cast<char*>(g_h + (size_t)grow * OUT_F) + tx * 16) = p;
        }
    }
}

// ===================================================================
// Fused kernel 1: GEMM tiles 0..509 interleaved with histogram blocks.
// blockIdx % 4 == 3 -> hist (170 blocks, grid-stride); else gemm.
// ===================================================================
#define K1_BLOCKS 680
#define K1_HIST   170

__global__ void fused1_kernel(const float* __restrict__ x,
                              const float* __restrict__ W,
                              const float* __restrict__ bias,
                              const int*   __restrict__ edst)
{
    extern __shared__ float smem[];
    if ((blockIdx.x & 3) == 3) {
        const int h = blockIdx.x >> 2;
        const int stride = K1_HIST * 256;
        for (int e = h * 256 + threadIdx.x; e < N_EDGES; e += stride)
            atomicAdd(&g_deg[edst[e]], 1);           // RED.32
    } else {
        const int g = blockIdx.x - (blockIdx.x >> 2);
        gemm_tile(x, W, bias, smem, g);
    }
}

// ===================================================================
// Fused kernel 2: GEMM tiles 510..781 interleaved with scatter blocks.
// blockIdx % 3 == 2 -> scatter (136 blocks, grid-stride); else gemm.
// ===================================================================
#define K2_BLOCKS 408
#define K2_SCAT   136

__global__ void fused2_kernel(const float* __restrict__ x,
                              const float* __restrict__ W,
                              const float* __restrict__ bias,
                              const int*   __restrict__ esrc,
                              const int*   __restrict__ edst,
                              const float* __restrict__ evals)
{
    extern __shared__ float smem[];
    if (blockIdx.x % 3 == 2) {
        const int s = blockIdx.x / 3;
        const int stride = K2_SCAT * 256;
        for (int e = s * 256 + threadIdx.x; e < N_EDGES; e += stride) {
            const int d   = edst[e];
            const int pos = atomicAdd(&g_cursor[d], 1);
            g_eperm[pos] = make_int2(esrc[e], __float_as_int(evals[e]));
        }
    } else {
        const int g = 510 + (blockIdx.x - blockIdx.x / 3);
        gemm_tile(x, W, bias, smem, g);
    }
}

// ===================================================================
// CSR build helpers: zero -> (hist in fused1) -> scan -> (scatter in fused2)
// ===================================================================
__global__ void zero_deg_kernel()
{
    const int i = blockIdx.x * blockDim.x + threadIdx.x;
    if (i < N_NODES) g_deg[i] = 0;
}

__global__ void scan1_kernel()
{
    __shared__ int s[1024];
    const int t   = threadIdx.x;
    const int gid = blockIdx.x * 1024 + t;
    const int v = (gid < N_NODES) ? g_deg[gid] : 0;
    s[t] = v;
    __syncthreads();
    #pragma unroll
    for (int o = 1; o < 1024; o <<= 1) {
        int a = (t >= o) ? s[t - o] : 0;
        __syncthreads();
        s[t] += a;
        __syncthreads();
    }
    if (gid < N_NODES) g_offs[gid] = s[t] - v;
    if (t == 1023) g_bsum[blockIdx.x] = s[t];
}

__global__ void scan2_kernel(int nblocks)
{
    __shared__ int s[128];
    const int t = threadIdx.x;
    const int v = (t < nblocks) ? g_bsum[t] : 0;
    s[t] = v;
    __syncthreads();
    #pragma unroll
    for (int o = 1; o < 128; o <<= 1) {
        int a = (t >= o) ? s[t - o] : 0;
        __syncthreads();
        s[t] += a;
        __syncthreads();
    }
    if (t < nblocks) g_bsum[t] = s[t] - v;
}

__global__ void scan3_kernel()
{
    const int gid = blockIdx.x * blockDim.x + threadIdx.x;
    if (gid < N_NODES) {
        const int o = g_offs[gid] + g_bsum[gid >> 10];
        g_offs[gid]   = o;
        g_cursor[gid] = o;
    }
    if (gid == 0) g_offs[N_NODES] = N_EDGES;
}

// ===================================================================
// CSR SpMM: warp per dst node, fp16 gather (256B/row), fp32 accumulate.
// Lane l owns features l*4..l*4+3 (one 8B load per edge). No atomics.
// ===================================================================
__global__ void spmm_csr_kernel(float* __restrict__ out)
{
    const int w = (blockIdx.x * blockDim.x + threadIdx.x) >> 5;
    if (w >= N_NODES) return;
    const int lane = threadIdx.x & 31;

    const int beg = __ldg(g_offs + w);
    const int end = __ldg(g_offs + w + 1);

    float4 acc = make_float4(0.f, 0.f, 0.f, 0.f);

    int e = beg;
    for (; e + 4 <= end; e += 4) {
        const int2 m0 = __ldg(g_eperm + e + 0);
        const int2 m1 = __ldg(g_eperm + e + 1);
        const int2 m2 = __ldg(g_eperm + e + 2);
        const int2 m3 = __ldg(g_eperm + e + 3);
        const uint2 u0 = __ldg(reinterpret_cast<const uint2*>(g_h + (size_t)m0.x * OUT_F) + lane);
        const uint2 u1 = __ldg(reinterpret_cast<const uint2*>(g_h + (size_t)m1.x * OUT_F) + lane);
        const uint2 u2 = __ldg(reinterpret_cast<const uint2*>(g_h + (size_t)m2.x * OUT_F) + lane);
        const uint2 u3 = __ldg(reinterpret_cast<const uint2*>(g_h + (size_t)m3.x * OUT_F) + lane);
        const float w0 = __int_as_float(m0.y), w1 = __int_as_float(m1.y);
        const float w2 = __int_as_float(m2.y), w3 = __int_as_float(m3.y);
        {
            const float2 a = __half22float2(*reinterpret_cast<const __half2*>(&u0.x));
            const float2 b = __half22float2(*reinterpret_cast<const __half2*>(&u0.y));
            acc.x += w0 * a.x; acc.y += w0 * a.y; acc.z += w0 * b.x; acc.w += w0 * b.y;
        }
        {
            const float2 a = __half22float2(*reinterpret_cast<const __half2*>(&u1.x));
            const float2 b = __half22float2(*reinterpret_cast<const __half2*>(&u1.y));
            acc.x += w1 * a.x; acc.y += w1 * a.y; acc.z += w1 * b.x; acc.w += w1 * b.y;
        }
        {
            const float2 a = __half22float2(*reinterpret_cast<const __half2*>(&u2.x));
            const float2 b = __half22float2(*reinterpret_cast<const __half2*>(&u2.y));
            acc.x += w2 * a.x; acc.y += w2 * a.y; acc.z += w2 * b.x; acc.w += w2 * b.y;
        }
        {
            const float2 a = __half22float2(*reinterpret_cast<const __half2*>(&u3.x));
            const float2 b = __half22float2(*reinterpret_cast<const __half2*>(&u3.y));
            acc.x += w3 * a.x; acc.y += w3 * a.y; acc.z += w3 * b.x; acc.w += w3 * b.y;
        }
    }
    for (; e < end; e++) {
        const int2 m = __ldg(g_eperm + e);
        const uint2 u = __ldg(reinterpret_cast<const uint2*>(g_h + (size_t)m.x * OUT_F) + lane);
        const float wv = __int_as_float(m.y);
        const float2 a = __half22float2(*reinterpret_cast<const __half2*>(&u.x));
        const float2 b = __half22float2(*reinterpret_cast<const __half2*>(&u.y));
        acc.x += wv * a.x; acc.y += wv * a.y; acc.z += wv * b.x; acc.w += wv * b.y;
    }

    reinterpret_cast<float4*>(out + (size_t)w * OUT_F)[lane] = acc;
}

// ===================================================================
extern "C" void kernel_launch(void* const* d_in, const int* in_sizes, int n_in,
                              void* d_out, int out_size)
{
    const float* x     = (const float*)d_in[0];
    const int*   esrc  = (const int*)  d_in[1];
    const int*   edst  = (const int*)  d_in[2];
    const float* evals = (const float*)d_in[3];
    const float* W     = (const float*)d_in[4];
    const float* bias  = (const float*)d_in[5];
    float*       out   = (float*)d_out;

    const int smem_gemm = 2 * 128 * 128 * (int)sizeof(float);   // 128 KB
    cudaFuncSetAttribute(fused1_kernel,
                         cudaFuncAttributeMaxDynamicSharedMemorySize, smem_gemm);
    cudaFuncSetAttribute(fused2_kernel,
                         cudaFuncAttributeMaxDynamicSharedMemorySize, smem_gemm);

    const int scan_blocks = (N_NODES + 1023) / 1024;            // 98

    zero_deg_kernel<<<(N_NODES + 1023) / 1024, 1024>>>();

    // GEMM part 1 (tiles 0..509) overlapped with histogram
    fused1_kernel<<<K1_BLOCKS, 256, smem_gemm>>>(x, W, bias, edst);

    scan1_kernel<<<scan_blocks, 1024>>>();
    scan2_kernel<<<1, 128>>>(scan_blocks);
    scan3_kernel<<<(N_NODES + 255) / 256, 256>>>();

    // GEMM part 2 (tiles 510..781) overlapped with edge scatter
    fused2_kernel<<<K2_BLOCKS, 256, smem_gemm>>>(x, W, bias, esrc, edst, evals);

    // atomic-free SpMM (fp16 gather, fp32 accumulate)
    const int spmm_blocks = (N_NODES * 32 + 255) / 256;
    spmm_csr_kernel<<<spmm_blocks, 256>>>(out);
}

// round 6
// speedup vs baseline: 3.3656x; 1.8049x over previous
#include <cuda_runtime.h>
#include <cuda_fp16.h>
#include <cstdint>

#define N_NODES 100000
#define N_EDGES 3200000
#define IN_F    256
#define OUT_F   128
#define GEMM_TILES ((N_NODES + 127) / 128)   // 782

// ---------------- device scratch (allocation-free) ----------------
__device__ __half g_h[(size_t)N_NODES * OUT_F];   // 25.6 MB projected features (fp16)
__device__ __half g_wt[OUT_F * IN_F];             // W^T as fp16 [128 n][256 k]
__device__ int    g_deg[N_NODES];
__device__ int    g_offs[N_NODES + 1];
__device__ int    g_cursor[N_NODES];
__device__ int    g_bsum[128];
__device__ int2   g_eperm[N_EDGES];

// ===================================================================
// HMMA GEMM: h = fp16(x @ W + bias) via mma.sync m16n8k16 (baseline PTX).
// CTA: 256 thr = 8 warps in 4(M)x2(N); tile 128x128, K=256 in 2 halves.
// Warp tile: 32(M) x 64(N) = 2 m-atoms x 8 n-atoms.
// smem: B = W^T [128][256] halves, row stride 264 (conflict-free);
//       A = x half-tile [128][128] halves, row stride 136.
// Fragment LDS.32 loads: bank = (4*(lane>>2) + (lane&3)) -> all distinct.
// ===================================================================
#define APAD 136   // halves per A row
#define BPAD 264   // halves per B row
#define SM_B    0
#define SM_A    (128 * BPAD)               // halves
#define SM_BIAS (SM_A + 128 * APAD)        // halves offset; bias stored as floats after
#define SM_HALVES (SM_BIAS + 256)          // bias = 128 floats = 256 halves
#define SM_BYTES  (SM_HALVES * 2)

__device__ __forceinline__ uint32_t lds32(const __half* p) {
    return *reinterpret_cast<const uint32_t*>(p);
}

__global__ void __launch_bounds__(256, 2) gemm_hmma_kernel(const float* __restrict__ x,
                                                           const float* __restrict__ bias)
{
    extern __shared__ __half smem[];
    __half* bs = smem + SM_B;
    __half* as = smem + SM_A;
    float*  bias_s = reinterpret_cast<float*>(smem + SM_BIAS);

    const int tid  = threadIdx.x;
    const int wid  = tid >> 5;
    const int lane = tid & 31;
    const int wm   = wid >> 1;          // 0..3  -> rows wm*32..+31
    const int wn   = wid & 1;           // 0..1  -> cols wn*64..+63
    const int g    = lane >> 2;         // group id 0..7
    const int t4   = lane & 3;          // thread in group
    const int row0 = blockIdx.x * 128;

    // stage B (W^T) once: 128 rows x 32 uint4 chunks
    {
        const uint4* wt4 = reinterpret_cast<const uint4*>(g_wt);
        #pragma unroll
        for (int i = tid; i < 4096; i += 256) {
            const int n = i >> 5, kc = i & 31;
            *reinterpret_cast<uint4*>(bs + n * BPAD + kc * 8) = wt4[n * 32 + kc];
        }
    }
    if (tid < 128) bias_s[tid] = bias[tid];

    float c[2][8][4];
    #pragma unroll
    for (int i = 0; i < 2; i++)
        #pragma unroll
        for (int j = 0; j < 8; j++)
            #pragma unroll
            for (int q = 0; q < 4; q++) c[i][j][q] = 0.f;

    const float4* xg = reinterpret_cast<const float4*>(x);
    const float4  z4 = make_float4(0.f, 0.f, 0.f, 0.f);

    #pragma unroll
    for (int h = 0; h < 2; h++) {
        __syncthreads();   // protect A buffer reuse (h=1) / orders B stage (h=0)
        // stage A half: rows row0..+127, k = h*128..+127, fp32 -> fp16
        #pragma unroll
        for (int i = tid; i < 2048; i += 256) {
            const int row = i >> 4, kc = i & 15;    // kc: 8-half chunk
            const int grow = row0 + row;
            float4 a = z4, b = z4;
            if (grow < N_NODES) {
                a = xg[(size_t)grow * 64 + h * 32 + kc * 2];
                b = xg[(size_t)grow * 64 + h * 32 + kc * 2 + 1];
            }
            uint4 p;
            *reinterpret_cast<__half2*>(&p.x) = __float22half2_rn(make_float2(a.x, a.y));
            *reinterpret_cast<__half2*>(&p.y) = __float22half2_rn(make_float2(a.z, a.w));
            *reinterpret_cast<__half2*>(&p.z) = __float22half2_rn(make_float2(b.x, b.y));
            *reinterpret_cast<__half2*>(&p.w) = __float22half2_rn(make_float2(b.z, b.w));
            *reinterpret_cast<uint4*>(as + row * APAD + kc * 8) = p;
        }
        __syncthreads();

        #pragma unroll
        for (int kk = 0; kk < 8; kk++) {
            const int kb = kk * 16;
            // A fragments: 2 m-atoms x 4 regs
            uint32_t afr[2][4];
            #pragma unroll
            for (int i = 0; i < 2; i++) {
                const int rb = wm * 32 + i * 16;
                const __half* ap = as + (size_t)(rb + g) * APAD + kb + t4 * 2;
                afr[i][0] = lds32(ap);                      // m=g,    k=t4*2
                afr[i][1] = lds32(ap + 8 * APAD);           // m=g+8
                afr[i][2] = lds32(ap + 8);                  // m=g,    k+8
                afr[i][3] = lds32(ap + 8 * APAD + 8);       // m=g+8,  k+8
            }
            // B fragments + MMA: 8 n-atoms. NOTE: B holds full K=256,
            // so the K-half offset h*128 MUST be applied here (R5 bugfix).
            #pragma unroll
            for (int j = 0; j < 8; j++) {
                const int nb = wn * 64 + j * 8;
                const __half* bp = bs + (size_t)(nb + g) * BPAD + h * 128 + kb + t4 * 2;
                const uint32_t b0 = lds32(bp);              // n=g, k=t4*2
                const uint32_t b1 = lds32(bp + 8);          // n=g, k+8
                #pragma unroll
                for (int i = 0; i < 2; i++) {
                    asm volatile(
                        "mma.sync.aligned.m16n8k16.row.col.f32.f16.f16.f32 "
                        "{%0,%1,%2,%3}, {%4,%5,%6,%7}, {%8,%9}, {%0,%1,%2,%3};"
                        : "+f"(c[i][j][0]), "+f"(c[i][j][1]),
                          "+f"(c[i][j][2]), "+f"(c[i][j][3])
                        : "r"(afr[i][0]), "r"(afr[i][1]), "r"(afr[i][2]), "r"(afr[i][3]),
                          "r"(b0), "r"(b1));
                }
            }
        }
    }

    // epilogue: add bias, convert to fp16, store half2 per (row, n-atom)
    #pragma unroll
    for (int i = 0; i < 2; i++) {
        const int r0 = row0 + wm * 32 + i * 16 + g;
        const int r1 = r0 + 8;
        #pragma unroll
        for (int j = 0; j < 8; j++) {
            const int col = wn * 64 + j * 8 + t4 * 2;
            const float2 bv = *reinterpret_cast<const float2*>(bias_s + col);
            if (r0 < N_NODES) {
                __half2 hv = __float22half2_rn(make_float2(c[i][j][0] + bv.x,
                                                           c[i][j][1] + bv.y));
                *reinterpret_cast<__half2*>(g_h + (size_t)r0 * OUT_F + col) = hv;
            }
            if (r1 < N_NODES) {
                __half2 hv = __float22half2_rn(make_float2(c[i][j][2] + bv.x,
                                                           c[i][j][3] + bv.y));
                *reinterpret_cast<__half2*>(g_h + (size_t)r1 * OUT_F + col) = hv;
            }
        }
    }
}

// ===================================================================
// prep: zero degree histogram + transpose W to fp16 (independent work)
// ===================================================================
__global__ void prep_kernel(const float* __restrict__ W)
{
    const int i = blockIdx.x * blockDim.x + threadIdx.x;
    if (i < N_NODES) g_deg[i] = 0;
    const int j = i - N_NODES;
    if (j >= 0 && j < IN_F * OUT_F) {
        const int k = j >> 7, n = j & 127;       // W[k][n], coalesced read
        g_wt[n * IN_F + k] = __float2half_rn(W[j]);
    }
}

__global__ void hist_kernel(const int* __restrict__ edst)
{
    const int e = blockIdx.x * blockDim.x + threadIdx.x;
    if (e < N_EDGES) atomicAdd(&g_deg[edst[e]], 1);
}

// shuffle-based block scan (1024), exclusive out, block totals to g_bsum
__global__ void scan1_kernel()
{
    __shared__ int wsum[32];
    const int t = threadIdx.x;
    const int gid = blockIdx.x * 1024 + t;
    const int v = (gid < N_NODES) ? g_deg[gid] : 0;
    int s = v;
    #pragma unroll
    for (int o = 1; o < 32; o <<= 1) {
        int n = __shfl_up_sync(0xffffffffu, s, o);
        if ((t & 31) >= o) s += n;
    }
    if ((t & 31) == 31) wsum[t >> 5] = s;
    __syncthreads();
    if (t < 32) {
        int ws = wsum[t];
        #pragma unroll
        for (int o = 1; o < 32; o <<= 1) {
            int n = __shfl_up_sync(0xffffffffu, ws, o);
            if (t >= o) ws += n;
        }
        wsum[t] = ws;
    }
    __syncthreads();
    const int base = (t >= 32) ? wsum[(t >> 5) - 1] : 0;
    const int incl = s + base;
    if (gid < N_NODES) g_offs[gid] = incl - v;
    if (t == 1023) g_bsum[blockIdx.x] = incl;
}

__global__ void scan2_kernel(int nb)
{
    __shared__ int wsum[4];
    const int t = threadIdx.x;            // 128 threads
    const int v = (t < nb) ? g_bsum[t] : 0;
    int s = v;
    #pragma unroll
    for (int o = 1; o < 32; o <<= 1) {
        int n = __shfl_up_sync(0xffffffffu, s, o);
        if ((t & 31) >= o) s += n;
    }
    if ((t & 31) == 31) wsum[t >> 5] = s;
    __syncthreads();
    int add = 0;
    #pragma unroll
    for (int w = 0; w < 3; w++) if (w < (t >> 5)) add += wsum[w];
    if (t < nb) g_bsum[t] = s + add - v;   // exclusive
}

__global__ void scan3_kernel()
{
    const int gid = blockIdx.x * blockDim.x + threadIdx.x;
    if (gid < N_NODES) {
        const int o = g_offs[gid] + g_bsum[gid >> 10];
        g_offs[gid]   = o;
        g_cursor[gid] = o;
    }
    if (gid == 0) g_offs[N_NODES] = N_EDGES;
}

__global__ void scatter_kernel(const int*   __restrict__ esrc,
                               const int*   __restrict__ edst,
                               const float* __restrict__ evals)
{
    const int e = blockIdx.x * blockDim.x + threadIdx.x;
    if (e >= N_EDGES) return;
    const int pos = atomicAdd(&g_cursor[edst[e]], 1);
    g_eperm[pos] = make_int2(esrc[e], __float_as_int(evals[e]));
}

// ===================================================================
// CSR SpMM: 16 lanes per dst node, uint4 (16B = 8 halves) gathers,
// fp32 register accumulation, no atomics.
// ===================================================================
__device__ __forceinline__ void fmaacc(float* acc, uint4 u, float w)
{
    const float2 a = __half22float2(*reinterpret_cast<const __half2*>(&u.x));
    const float2 b = __half22float2(*reinterpret_cast<const __half2*>(&u.y));
    const float2 c = __half22float2(*reinterpret_cast<const __half2*>(&u.z));
    const float2 d = __half22float2(*reinterpret_cast<const __half2*>(&u.w));
    acc[0] += w * a.x; acc[1] += w * a.y; acc[2] += w * b.x; acc[3] += w * b.y;
    acc[4] += w * c.x; acc[5] += w * c.y; acc[6] += w * d.x; acc[7] += w * d.y;
}

__global__ void spmm_csr_kernel(float* __restrict__ out)
{
    const int gt = blockIdx.x * blockDim.x + threadIdx.x;
    const int node = gt >> 4;
    if (node >= N_NODES) return;
    const int sl = threadIdx.x & 15;

    const int beg = __ldg(g_offs + node);
    const int end = __ldg(g_offs + node + 1);

    float acc[8];
    #pragma unroll
    for (int i = 0; i < 8; i++) acc[i] = 0.f;

    int e = beg;
    for (; e + 4 <= end; e += 4) {
        const int2 m0 = __ldg(g_eperm + e + 0);
        const int2 m1 = __ldg(g_eperm + e + 1);
        const int2 m2 = __ldg(g_eperm + e + 2);
        const int2 m3 = __ldg(g_eperm + e + 3);
        const uint4 v0 = __ldg(reinterpret_cast<const uint4*>(g_h + (size_t)m0.x * OUT_F) + sl);
        const uint4 v1 = __ldg(reinterpret_cast<const uint4*>(g_h + (size_t)m1.x * OUT_F) + sl);
        const uint4 v2 = __ldg(reinterpret_cast<const uint4*>(g_h + (size_t)m2.x * OUT_F) + sl);
        const uint4 v3 = __ldg(reinterpret_cast<const uint4*>(g_h + (size_t)m3.x * OUT_F) + sl);
        fmaacc(acc, v0, __int_as_float(m0.y));
        fmaacc(acc, v1, __int_as_float(m1.y));
        fmaacc(acc, v2, __int_as_float(m2.y));
        fmaacc(acc, v3, __int_as_float(m3.y));
    }
    for (; e < end; e++) {
        const int2 m = __ldg(g_eperm + e);
        const uint4 v = __ldg(reinterpret_cast<const uint4*>(g_h + (size_t)m.x * OUT_F) + sl);
        fmaacc(acc, v, __int_as_float(m.y));
    }

    float4* op = reinterpret_cast<float4*>(out + (size_t)node * OUT_F);
    op[sl * 2 + 0] = make_float4(acc[0], acc[1], acc[2], acc[3]);
    op[sl * 2 + 1] = make_float4(acc[4], acc[5], acc[6], acc[7]);
}

// ===================================================================
extern "C" void kernel_launch(void* const* d_in, const int* in_sizes, int n_in,
                              void* d_out, int out_size)
{
    const float* x     = (const float*)d_in[0];
    const int*   esrc  = (const int*)  d_in[1];
    const int*   edst  = (const int*)  d_in[2];
    const float* evals = (const float*)d_in[3];
    const float* W     = (const float*)d_in[4];
    const float* bias  = (const float*)d_in[5];
    float*       out   = (float*)d_out;

    cudaFuncSetAttribute(gemm_hmma_kernel,
                         cudaFuncAttributeMaxDynamicSharedMemorySize, SM_BYTES);

    const int scan_blocks = (N_NODES + 1023) / 1024;            // 98

    prep_kernel<<<(N_NODES + IN_F * OUT_F + 255) / 256, 256>>>(W);
    gemm_hmma_kernel<<<GEMM_TILES, 256, SM_BYTES>>>(x, bias);

    hist_kernel<<<(N_EDGES + 255) / 256, 256>>>(edst);
    scan1_kernel<<<scan_blocks, 1024>>>();
    scan2_kernel<<<1, 128>>>(scan_blocks);
    scan3_kernel<<<(N_NODES + 255) / 256, 256>>>();
    scatter_kernel<<<(N_EDGES + 255) / 256, 256>>>(esrc, edst, evals);

    spmm_csr_kernel<<<(N_NODES * 16 + 255) / 256, 256>>>(out);
}

// round 7
// speedup vs baseline: 3.5329x; 1.0497x over previous
#include <cuda_runtime.h>
#include <cuda_fp16.h>
#include <cstdint>

#define N_NODES 100000
#define N_EDGES 3200000
#define IN_F    256
#define OUT_F   128
#define GEMM_TILES ((N_NODES + 127) / 128)   // 782

// ---------------- device scratch (allocation-free) ----------------
__device__ __half g_h[(size_t)N_NODES * OUT_F];   // 25.6 MB projected features (fp16)
__device__ __half g_wt[OUT_F * IN_F];             // W^T as fp16 [128 n][256 k]
__device__ int    g_deg[N_NODES];
__device__ int    g_offs[N_NODES + 1];
__device__ int    g_cursor[N_NODES];
__device__ int    g_bsum[128];
__device__ int2   g_eperm[N_EDGES];

// ===================================================================
// HMMA GEMM: h = fp16(x @ W + bias) via mma.sync m16n8k16 (baseline PTX).
// CTA: 256 thr = 8 warps in 4(M)x2(N); tile 128x128, K=256 in 2 halves.
// ===================================================================
#define APAD 136   // halves per A row
#define BPAD 264   // halves per B row
#define SM_B    0
#define SM_A    (128 * BPAD)
#define SM_BIAS (SM_A + 128 * APAD)
#define SM_HALVES (SM_BIAS + 256)
#define SM_BYTES  (SM_HALVES * 2)

__device__ __forceinline__ uint32_t lds32(const __half* p) {
    return *reinterpret_cast<const uint32_t*>(p);
}

__global__ void __launch_bounds__(256, 2) gemm_hmma_kernel(const float* __restrict__ x,
                                                           const float* __restrict__ bias)
{
    extern __shared__ __half smem[];
    __half* bs = smem + SM_B;
    __half* as = smem + SM_A;
    float*  bias_s = reinterpret_cast<float*>(smem + SM_BIAS);

    const int tid  = threadIdx.x;
    const int wid  = tid >> 5;
    const int lane = tid & 31;
    const int wm   = wid >> 1;
    const int wn   = wid & 1;
    const int g    = lane >> 2;
    const int t4   = lane & 3;
    const int row0 = blockIdx.x * 128;

    {
        const uint4* wt4 = reinterpret_cast<const uint4*>(g_wt);
        #pragma unroll
        for (int i = tid; i < 4096; i += 256) {
            const int n = i >> 5, kc = i & 31;
            *reinterpret_cast<uint4*>(bs + n * BPAD + kc * 8) = wt4[n * 32 + kc];
        }
    }
    if (tid < 128) bias_s[tid] = bias[tid];

    float c[2][8][4];
    #pragma unroll
    for (int i = 0; i < 2; i++)
        #pragma unroll
        for (int j = 0; j < 8; j++)
            #pragma unroll
            for (int q = 0; q < 4; q++) c[i][j][q] = 0.f;

    const float4* xg = reinterpret_cast<const float4*>(x);
    const float4  z4 = make_float4(0.f, 0.f, 0.f, 0.f);

    #pragma unroll
    for (int h = 0; h < 2; h++) {
        __syncthreads();
        #pragma unroll
        for (int i = tid; i < 2048; i += 256) {
            const int row = i >> 4, kc = i & 15;
            const int grow = row0 + row;
            float4 a = z4, b = z4;
            if (grow < N_NODES) {
                a = xg[(size_t)grow * 64 + h * 32 + kc * 2];
                b = xg[(size_t)grow * 64 + h * 32 + kc * 2 + 1];
            }
            uint4 p;
            *reinterpret_cast<__half2*>(&p.x) = __float22half2_rn(make_float2(a.x, a.y));
            *reinterpret_cast<__half2*>(&p.y) = __float22half2_rn(make_float2(a.z, a.w));
            *reinterpret_cast<__half2*>(&p.z) = __float22half2_rn(make_float2(b.x, b.y));
            *reinterpret_cast<__half2*>(&p.w) = __float22half2_rn(make_float2(b.z, b.w));
            *reinterpret_cast<uint4*>(as + row * APAD + kc * 8) = p;
        }
        __syncthreads();

        #pragma unroll
        for (int kk = 0; kk < 8; kk++) {
            const int kb = kk * 16;
            uint32_t afr[2][4];
            #pragma unroll
            for (int i = 0; i < 2; i++) {
                const int rb = wm * 32 + i * 16;
                const __half* ap = as + (size_t)(rb + g) * APAD + kb + t4 * 2;
                afr[i][0] = lds32(ap);
                afr[i][1] = lds32(ap + 8 * APAD);
                afr[i][2] = lds32(ap + 8);
                afr[i][3] = lds32(ap + 8 * APAD + 8);
            }
            #pragma unroll
            for (int j = 0; j < 8; j++) {
                const int nb = wn * 64 + j * 8;
                const __half* bp = bs + (size_t)(nb + g) * BPAD + h * 128 + kb + t4 * 2;
                const uint32_t b0 = lds32(bp);
                const uint32_t b1 = lds32(bp + 8);
                #pragma unroll
                for (int i = 0; i < 2; i++) {
                    asm volatile(
                        "mma.sync.aligned.m16n8k16.row.col.f32.f16.f16.f32 "
                        "{%0,%1,%2,%3}, {%4,%5,%6,%7}, {%8,%9}, {%0,%1,%2,%3};"
                        : "+f"(c[i][j][0]), "+f"(c[i][j][1]),
                          "+f"(c[i][j][2]), "+f"(c[i][j][3])
                        : "r"(afr[i][0]), "r"(afr[i][1]), "r"(afr[i][2]), "r"(afr[i][3]),
                          "r"(b0), "r"(b1));
                }
            }
        }
    }

    #pragma unroll
    for (int i = 0; i < 2; i++) {
        const int r0 = row0 + wm * 32 + i * 16 + g;
        const int r1 = r0 + 8;
        #pragma unroll
        for (int j = 0; j < 8; j++) {
            const int col = wn * 64 + j * 8 + t4 * 2;
            const float2 bv = *reinterpret_cast<const float2*>(bias_s + col);
            if (r0 < N_NODES) {
                __half2 hv = __float22half2_rn(make_float2(c[i][j][0] + bv.x,
                                                           c[i][j][1] + bv.y));
                *reinterpret_cast<__half2*>(g_h + (size_t)r0 * OUT_F + col) = hv;
            }
            if (r1 < N_NODES) {
                __half2 hv = __float22half2_rn(make_float2(c[i][j][2] + bv.x,
                                                           c[i][j][3] + bv.y));
                *reinterpret_cast<__half2*>(g_h + (size_t)r1 * OUT_F + col) = hv;
            }
        }
    }
}

// ===================================================================
// branch-A prep: transpose W to fp16 (feeds GEMM only)
// ===================================================================
__global__ void wt_kernel(const float* __restrict__ W)
{
    const int j = blockIdx.x * blockDim.x + threadIdx.x;
    if (j < IN_F * OUT_F) {
        const int k = j >> 7, n = j & 127;       // W[k][n], coalesced read
        g_wt[n * IN_F + k] = __float2half_rn(W[j]);
    }
}

// ===================================================================
// branch-B: zero -> hist -> scan1 -> scan23 -> scatter
// ===================================================================
__global__ void zero_deg_kernel()
{
    const int i = blockIdx.x * blockDim.x + threadIdx.x;
    if (i < N_NODES) g_deg[i] = 0;
}

__global__ void hist_kernel(const int* __restrict__ edst)
{
    const int e = blockIdx.x * blockDim.x + threadIdx.x;
    if (e < N_EDGES) atomicAdd(&g_deg[edst[e]], 1);
}

// shuffle-based block scan (1024), exclusive out, block totals to g_bsum
__global__ void scan1_kernel()
{
    __shared__ int wsum[32];
    const int t = threadIdx.x;
    const int gid = blockIdx.x * 1024 + t;
    const int v = (gid < N_NODES) ? g_deg[gid] : 0;
    int s = v;
    #pragma unroll
    for (int o = 1; o < 32; o <<= 1) {
        int n = __shfl_up_sync(0xffffffffu, s, o);
        if ((t & 31) >= o) s += n;
    }
    if ((t & 31) == 31) wsum[t >> 5] = s;
    __syncthreads();
    if (t < 32) {
        int ws = wsum[t];
        #pragma unroll
        for (int o = 1; o < 32; o <<= 1) {
            int n = __shfl_up_sync(0xffffffffu, ws, o);
            if (t >= o) ws += n;
        }
        wsum[t] = ws;
    }
    __syncthreads();
    const int base = (t >= 32) ? wsum[(t >> 5) - 1] : 0;
    const int incl = s + base;
    if (gid < N_NODES) g_offs[gid] = incl - v;
    if (t == 1023) g_bsum[blockIdx.x] = incl;
}

// merged scan2+scan3: each block re-reduces the <=98 block sums below it,
// then applies the prefix to its 1024 offsets and seeds the cursors.
__global__ void scan23_kernel()
{
    __shared__ int wpart[4];
    __shared__ int prefix_s;
    const int t = threadIdx.x;                   // 1024 threads
    if (t < 128) {
        int v = (t < (int)blockIdx.x) ? g_bsum[t] : 0;
        #pragma unroll
        for (int o = 16; o > 0; o >>= 1)
            v += __shfl_down_sync(0xffffffffu, v, o);
        if ((t & 31) == 0) wpart[t >> 5] = v;
    }
    __syncthreads();
    if (t == 0) prefix_s = wpart[0] + wpart[1] + wpart[2] + wpart[3];
    __syncthreads();
    const int gid = blockIdx.x * 1024 + t;
    if (gid < N_NODES) {
        const int o = g_offs[gid] + prefix_s;
        g_offs[gid]   = o;
        g_cursor[gid] = o;
    }
    if (gid == 0) g_offs[N_NODES] = N_EDGES;
}

__global__ void scatter_kernel(const int*   __restrict__ esrc,
                               const int*   __restrict__ edst,
                               const float* __restrict__ evals)
{
    const int e = blockIdx.x * blockDim.x + threadIdx.x;
    if (e >= N_EDGES) return;
    const int pos = atomicAdd(&g_cursor[edst[e]], 1);
    g_eperm[pos] = make_int2(esrc[e], __float_as_int(evals[e]));
}

// ===================================================================
// CSR SpMM: 16 lanes per dst node, uint4 (16B = 8 halves) gathers,
// fp32 register accumulation, no atomics.
// ===================================================================
__device__ __forceinline__ void fmaacc(float* acc, uint4 u, float w)
{
    const float2 a = __half22float2(*reinterpret_cast<const __half2*>(&u.x));
    const float2 b = __half22float2(*reinterpret_cast<const __half2*>(&u.y));
    const float2 c = __half22float2(*reinterpret_cast<const __half2*>(&u.z));
    const float2 d = __half22float2(*reinterpret_cast<const __half2*>(&u.w));
    acc[0] += w * a.x; acc[1] += w * a.y; acc[2] += w * b.x; acc[3] += w * b.y;
    acc[4] += w * c.x; acc[5] += w * c.y; acc[6] += w * d.x; acc[7] += w * d.y;
}

__global__ void spmm_csr_kernel(float* __restrict__ out)
{
    const int gt = blockIdx.x * blockDim.x + threadIdx.x;
    const int node = gt >> 4;
    if (node >= N_NODES) return;
    const int sl = threadIdx.x & 15;

    const int beg = __ldg(g_offs + node);
    const int end = __ldg(g_offs + node + 1);

    float acc[8];
    #pragma unroll
    for (int i = 0; i < 8; i++) acc[i] = 0.f;

    int e = beg;
    for (; e + 4 <= end; e += 4) {
        const int2 m0 = __ldg(g_eperm + e + 0);
        const int2 m1 = __ldg(g_eperm + e + 1);
        const int2 m2 = __ldg(g_eperm + e + 2);
        const int2 m3 = __ldg(g_eperm + e + 3);
        const uint4 v0 = __ldg(reinterpret_cast<const uint4*>(g_h + (size_t)m0.x * OUT_F) + sl);
        const uint4 v1 = __ldg(reinterpret_cast<const uint4*>(g_h + (size_t)m1.x * OUT_F) + sl);
        const uint4 v2 = __ldg(reinterpret_cast<const uint4*>(g_h + (size_t)m2.x * OUT_F) + sl);
        const uint4 v3 = __ldg(reinterpret_cast<const uint4*>(g_h + (size_t)m3.x * OUT_F) + sl);
        fmaacc(acc, v0, __int_as_float(m0.y));
        fmaacc(acc, v1, __int_as_float(m1.y));
        fmaacc(acc, v2, __int_as_float(m2.y));
        fmaacc(acc, v3, __int_as_float(m3.y));
    }
    for (; e < end; e++) {
        const int2 m = __ldg(g_eperm + e);
        const uint4 v = __ldg(reinterpret_cast<const uint4*>(g_h + (size_t)m.x * OUT_F) + sl);
        fmaacc(acc, v, __int_as_float(m.y));
    }

    float4* op = reinterpret_cast<float4*>(out + (size_t)node * OUT_F);
    op[sl * 2 + 0] = make_float4(acc[0], acc[1], acc[2], acc[3]);
    op[sl * 2 + 1] = make_float4(acc[4], acc[5], acc[6], acc[7]);
}

// ===================================================================
extern "C" void kernel_launch(void* const* d_in, const int* in_sizes, int n_in,
                              void* d_out, int out_size)
{
    const float* x     = (const float*)d_in[0];
    const int*   esrc  = (const int*)  d_in[1];
    const int*   edst  = (const int*)  d_in[2];
    const float* evals = (const float*)d_in[3];
    const float* W     = (const float*)d_in[4];
    const float* bias  = (const float*)d_in[5];
    float*       out   = (float*)d_out;

    cudaFuncSetAttribute(gemm_hmma_kernel,
                         cudaFuncAttributeMaxDynamicSharedMemorySize, SM_BYTES);

    // fork a non-blocking side stream into the capture graph for the GEMM
    // branch (independent of the CSR build until spmm). Streams/events are
    // host objects (no device allocation); intentionally not destroyed while
    // a capture referencing them may be in flight.
    cudaStream_t s2;
    cudaEvent_t evFork, evJoin;
    cudaStreamCreateWithFlags(&s2, cudaStreamNonBlocking);
    cudaEventCreateWithFlags(&evFork, cudaEventDisableTiming);
    cudaEventCreateWithFlags(&evJoin, cudaEventDisableTiming);

    cudaEventRecord(evFork, 0);
    cudaStreamWaitEvent(s2, evFork, 0);

    // branch A (side stream): W transpose + HMMA GEMM
    wt_kernel<<<(IN_F * OUT_F + 255) / 256, 256, 0, s2>>>(W);
    gemm_hmma_kernel<<<GEMM_TILES, 256, SM_BYTES, s2>>>(x, bias);

    // branch B (main stream): CSR-by-dst build
    zero_deg_kernel<<<(N_NODES + 1023) / 1024, 1024>>>();
    hist_kernel<<<(N_EDGES + 255) / 256, 256>>>(edst);
    scan1_kernel<<<(N_NODES + 1023) / 1024, 1024>>>();
    scan23_kernel<<<(N_NODES + 1023) / 1024, 1024>>>();
    scatter_kernel<<<(N_EDGES + 255) / 256, 256>>>(esrc, edst, evals);

    // join, then SpMM
    cudaEventRecord(evJoin, s2);
    cudaStreamWaitEvent(0, evJoin, 0);
    spmm_csr_kernel<<<(N_NODES * 16 + 255) / 256, 256>>>(out);
}

// round 8
// speedup vs baseline: 3.5733x; 1.0114x over previous
#include <cuda_runtime.h>
#include <cuda_fp16.h>
#include <cstdint>

#define N_NODES 100000
#define N_EDGES 3200000
#define IN_F    256
#define OUT_F   128
#define GEMM_TILES ((N_NODES + 127) / 128)   // 782

// ---------------- device scratch (allocation-free) ----------------
__device__ __half    g_h[(size_t)N_NODES * OUT_F];   // 25.6 MB projected features (fp16)
__device__ __half    g_wt[OUT_F * IN_F];             // W^T as fp16 [128 n][256 k]
__device__ int       g_deg[N_NODES];
__device__ int       g_offs[N_NODES + 1];
__device__ int       g_cursor[N_NODES];
__device__ int       g_bsum[128];
__device__ unsigned  g_eperm[N_EDGES];               // packed (src<<15 | val_q15), 12.8 MB

// ===================================================================
// HMMA GEMM: h = fp16(x @ W + bias) via mma.sync m16n8k16 (baseline PTX).
// CTA: 256 thr = 8 warps in 4(M)x2(N); tile 128x128, K=256 in 2 halves.
// ===================================================================
#define APAD 136   // halves per A row
#define BPAD 264   // halves per B row
#define SM_B    0
#define SM_A    (128 * BPAD)
#define SM_BIAS (SM_A + 128 * APAD)
#define SM_HALVES (SM_BIAS + 256)
#define SM_BYTES  (SM_HALVES * 2)

__device__ __forceinline__ uint32_t lds32(const __half* p) {
    return *reinterpret_cast<const uint32_t*>(p);
}

__global__ void __launch_bounds__(256, 2) gemm_hmma_kernel(const float* __restrict__ x,
                                                           const float* __restrict__ bias)
{
    extern __shared__ __half smem[];
    __half* bs = smem + SM_B;
    __half* as = smem + SM_A;
    float*  bias_s = reinterpret_cast<float*>(smem + SM_BIAS);

    const int tid  = threadIdx.x;
    const int wid  = tid >> 5;
    const int lane = tid & 31;
    const int wm   = wid >> 1;
    const int wn   = wid & 1;
    const int g    = lane >> 2;
    const int t4   = lane & 3;
    const int row0 = blockIdx.x * 128;

    {
        const uint4* wt4 = reinterpret_cast<const uint4*>(g_wt);
        #pragma unroll
        for (int i = tid; i < 4096; i += 256) {
            const int n = i >> 5, kc = i & 31;
            *reinterpret_cast<uint4*>(bs + n * BPAD + kc * 8) = wt4[n * 32 + kc];
        }
    }
    if (tid < 128) bias_s[tid] = bias[tid];

    float c[2][8][4];
    #pragma unroll
    for (int i = 0; i < 2; i++)
        #pragma unroll
        for (int j = 0; j < 8; j++)
            #pragma unroll
            for (int q = 0; q < 4; q++) c[i][j][q] = 0.f;

    const float4* xg = reinterpret_cast<const float4*>(x);
    const float4  z4 = make_float4(0.f, 0.f, 0.f, 0.f);

    #pragma unroll
    for (int h = 0; h < 2; h++) {
        __syncthreads();
        #pragma unroll
        for (int i = tid; i < 2048; i += 256) {
            const int row = i >> 4, kc = i & 15;
            const int grow = row0 + row;
            float4 a = z4, b = z4;
            if (grow < N_NODES) {
                a = xg[(size_t)grow * 64 + h * 32 + kc * 2];
                b = xg[(size_t)grow * 64 + h * 32 + kc * 2 + 1];
            }
            uint4 p;
            *reinterpret_cast<__half2*>(&p.x) = __float22half2_rn(make_float2(a.x, a.y));
            *reinterpret_cast<__half2*>(&p.y) = __float22half2_rn(make_float2(a.z, a.w));
            *reinterpret_cast<__half2*>(&p.z) = __float22half2_rn(make_float2(b.x, b.y));
            *reinterpret_cast<__half2*>(&p.w) = __float22half2_rn(make_float2(b.z, b.w));
            *reinterpret_cast<uint4*>(as + row * APAD + kc * 8) = p;
        }
        __syncthreads();

        #pragma unroll
        for (int kk = 0; kk < 8; kk++) {
            const int kb = kk * 16;
            uint32_t afr[2][4];
            #pragma unroll
            for (int i = 0; i < 2; i++) {
                const int rb = wm * 32 + i * 16;
                const __half* ap = as + (size_t)(rb + g) * APAD + kb + t4 * 2;
                afr[i][0] = lds32(ap);
                afr[i][1] = lds32(ap + 8 * APAD);
                afr[i][2] = lds32(ap + 8);
                afr[i][3] = lds32(ap + 8 * APAD + 8);
            }
            #pragma unroll
            for (int j = 0; j < 8; j++) {
                const int nb = wn * 64 + j * 8;
                const __half* bp = bs + (size_t)(nb + g) * BPAD + h * 128 + kb + t4 * 2;
                const uint32_t b0 = lds32(bp);
                const uint32_t b1 = lds32(bp + 8);
                #pragma unroll
                for (int i = 0; i < 2; i++) {
                    asm volatile(
                        "mma.sync.aligned.m16n8k16.row.col.f32.f16.f16.f32 "
                        "{%0,%1,%2,%3}, {%4,%5,%6,%7}, {%8,%9}, {%0,%1,%2,%3};"
                        : "+f"(c[i][j][0]), "+f"(c[i][j][1]),
                          "+f"(c[i][j][2]), "+f"(c[i][j][3])
                        : "r"(afr[i][0]), "r"(afr[i][1]), "r"(afr[i][2]), "r"(afr[i][3]),
                          "r"(b0), "r"(b1));
                }
            }
        }
    }

    #pragma unroll
    for (int i = 0; i < 2; i++) {
        const int r0 = row0 + wm * 32 + i * 16 + g;
        const int r1 = r0 + 8;
        #pragma unroll
        for (int j = 0; j < 8; j++) {
            const int col = wn * 64 + j * 8 + t4 * 2;
            const float2 bv = *reinterpret_cast<const float2*>(bias_s + col);
            if (r0 < N_NODES) {
                __half2 hv = __float22half2_rn(make_float2(c[i][j][0] + bv.x,
                                                           c[i][j][1] + bv.y));
                *reinterpret_cast<__half2*>(g_h + (size_t)r0 * OUT_F + col) = hv;
            }
            if (r1 < N_NODES) {
                __half2 hv = __float22half2_rn(make_float2(c[i][j][2] + bv.x,
                                                           c[i][j][3] + bv.y));
                *reinterpret_cast<__half2*>(g_h + (size_t)r1 * OUT_F + col) = hv;
            }
        }
    }
}

// ===================================================================
// branch-A prep: transpose W to fp16 (feeds GEMM only)
// ===================================================================
__global__ void wt_kernel(const float* __restrict__ W)
{
    const int j = blockIdx.x * blockDim.x + threadIdx.x;
    if (j < IN_F * OUT_F) {
        const int k = j >> 7, n = j & 127;       // W[k][n], coalesced read
        g_wt[n * IN_F + k] = __float2half_rn(W[j]);
    }
}

// ===================================================================
// branch-B: zero -> hist(x4) -> scan1 -> scan23 -> scatter(x4)
// ===================================================================
__global__ void zero_deg_kernel()
{
    const int i = blockIdx.x * blockDim.x + threadIdx.x;
    if (i < N_NODES) g_deg[i] = 0;
}

// 4 edges per thread (N_EDGES % 4 == 0)
__global__ void hist_kernel(const int* __restrict__ edst)
{
    const int e4 = (blockIdx.x * blockDim.x + threadIdx.x) * 4;
    if (e4 >= N_EDGES) return;
    const int4 d = *reinterpret_cast<const int4*>(edst + e4);
    atomicAdd(&g_deg[d.x], 1);
    atomicAdd(&g_deg[d.y], 1);
    atomicAdd(&g_deg[d.z], 1);
    atomicAdd(&g_deg[d.w], 1);
}

// shuffle-based block scan (1024), exclusive out, block totals to g_bsum
__global__ void scan1_kernel()
{
    __shared__ int wsum[32];
    const int t = threadIdx.x;
    const int gid = blockIdx.x * 1024 + t;
    const int v = (gid < N_NODES) ? g_deg[gid] : 0;
    int s = v;
    #pragma unroll
    for (int o = 1; o < 32; o <<= 1) {
        int n = __shfl_up_sync(0xffffffffu, s, o);
        if ((t & 31) >= o) s += n;
    }
    if ((t & 31) == 31) wsum[t >> 5] = s;
    __syncthreads();
    if (t < 32) {
        int ws = wsum[t];
        #pragma unroll
        for (int o = 1; o < 32; o <<= 1) {
            int n = __shfl_up_sync(0xffffffffu, ws, o);
            if (t >= o) ws += n;
        }
        wsum[t] = ws;
    }
    __syncthreads();
    const int base = (t >= 32) ? wsum[(t >> 5) - 1] : 0;
    const int incl = s + base;
    if (gid < N_NODES) g_offs[gid] = incl - v;
    if (t == 1023) g_bsum[blockIdx.x] = incl;
}

// merged scan2+scan3: each block re-reduces the <=98 block sums below it,
// then applies the prefix to its 1024 offsets and seeds the cursors.
__global__ void scan23_kernel()
{
    __shared__ int wpart[4];
    __shared__ int prefix_s;
    const int t = threadIdx.x;                   // 1024 threads
    if (t < 128) {
        int v = (t < (int)blockIdx.x) ? g_bsum[t] : 0;
        #pragma unroll
        for (int o = 16; o > 0; o >>= 1)
            v += __shfl_down_sync(0xffffffffu, v, o);
        if ((t & 31) == 0) wpart[t >> 5] = v;
    }
    __syncthreads();
    if (t == 0) prefix_s = wpart[0] + wpart[1] + wpart[2] + wpart[3];
    __syncthreads();
    const int gid = blockIdx.x * 1024 + t;
    if (gid < N_NODES) {
        const int o = g_offs[gid] + prefix_s;
        g_offs[gid]   = o;
        g_cursor[gid] = o;
    }
    if (gid == 0) g_offs[N_NODES] = N_EDGES;
}

// pack (src, val) -> 32 bits: src in [0,100000) needs 17 bits; val -> 15-bit
// fixed point (abs err <= 3e-5, negligible vs fp16-path error budget).
__device__ __forceinline__ unsigned pack_edge(int src, float val)
{
    int q = __float2int_rn(val * 32768.f);
    q = min(q, 32767);
    return ((unsigned)src << 15) | (unsigned)q;
}

// 4 edges per thread
__global__ void scatter_kernel(const int*   __restrict__ esrc,
                               const int*   __restrict__ edst,
                               const float* __restrict__ evals)
{
    const int e4 = (blockIdx.x * blockDim.x + threadIdx.x) * 4;
    if (e4 >= N_EDGES) return;
    const int4   s = *reinterpret_cast<const int4*>(esrc + e4);
    const int4   d = *reinterpret_cast<const int4*>(edst + e4);
    const float4 v = *reinterpret_cast<const float4*>(evals + e4);
    int p0 = atomicAdd(&g_cursor[d.x], 1);
    int p1 = atomicAdd(&g_cursor[d.y], 1);
    int p2 = atomicAdd(&g_cursor[d.z], 1);
    int p3 = atomicAdd(&g_cursor[d.w], 1);
    g_eperm[p0] = pack_edge(s.x, v.x);
    g_eperm[p1] = pack_edge(s.y, v.y);
    g_eperm[p2] = pack_edge(s.z, v.z);
    g_eperm[p3] = pack_edge(s.w, v.w);
}

// ===================================================================
// CSR SpMM: 16 lanes per dst node, uint4 (16B = 8 halves) gathers,
// fp32 register accumulation, no atomics. Packed 4B edge records.
// ===================================================================
__device__ __forceinline__ void fmaacc(float* acc, uint4 u, float w)
{
    const float2 a = __half22float2(*reinterpret_cast<const __half2*>(&u.x));
    const float2 b = __half22float2(*reinterpret_cast<const __half2*>(&u.y));
    const float2 c = __half22float2(*reinterpret_cast<const __half2*>(&u.z));
    const float2 d = __half22float2(*reinterpret_cast<const __half2*>(&u.w));
    acc[0] += w * a.x; acc[1] += w * a.y; acc[2] += w * b.x; acc[3] += w * b.y;
    acc[4] += w * c.x; acc[5] += w * c.y; acc[6] += w * d.x; acc[7] += w * d.y;
}

__global__ void spmm_csr_kernel(float* __restrict__ out)
{
    const int gt = blockIdx.x * blockDim.x + threadIdx.x;
    const int node = gt >> 4;
    if (node >= N_NODES) return;
    const int sl = threadIdx.x & 15;

    const int beg = __ldg(g_offs + node);
    const int end = __ldg(g_offs + node + 1);

    float acc[8];
    #pragma unroll
    for (int i = 0; i < 8; i++) acc[i] = 0.f;

    const float qs = 1.0f / 32768.0f;

    int e = beg;
    for (; e + 4 <= end; e += 4) {
        const unsigned m0 = __ldg(g_eperm + e + 0);
        const unsigned m1 = __ldg(g_eperm + e + 1);
        const unsigned m2 = __ldg(g_eperm + e + 2);
        const unsigned m3 = __ldg(g_eperm + e + 3);
        const uint4 v0 = __ldg(reinterpret_cast<const uint4*>(g_h + (size_t)(m0 >> 15) * OUT_F) + sl);
        const uint4 v1 = __ldg(reinterpret_cast<const uint4*>(g_h + (size_t)(m1 >> 15) * OUT_F) + sl);
        const uint4 v2 = __ldg(reinterpret_cast<const uint4*>(g_h + (size_t)(m2 >> 15) * OUT_F) + sl);
        const uint4 v3 = __ldg(reinterpret_cast<const uint4*>(g_h + (size_t)(m3 >> 15) * OUT_F) + sl);
        fmaacc(acc, v0, (float)(m0 & 32767u) * qs);
        fmaacc(acc, v1, (float)(m1 & 32767u) * qs);
        fmaacc(acc, v2, (float)(m2 & 32767u) * qs);
        fmaacc(acc, v3, (float)(m3 & 32767u) * qs);
    }
    for (; e < end; e++) {
        const unsigned m = __ldg(g_eperm + e);
        const uint4 v = __ldg(reinterpret_cast<const uint4*>(g_h + (size_t)(m >> 15) * OUT_F) + sl);
        fmaacc(acc, v, (float)(m & 32767u) * qs);
    }

    float4* op = reinterpret_cast<float4*>(out + (size_t)node * OUT_F);
    op[sl * 2 + 0] = make_float4(acc[0], acc[1], acc[2], acc[3]);
    op[sl * 2 + 1] = make_float4(acc[4], acc[5], acc[6], acc[7]);
}

// ===================================================================
extern "C" void kernel_launch(void* const* d_in, const int* in_sizes, int n_in,
                              void* d_out, int out_size)
{
    const float* x     = (const float*)d_in[0];
    const int*   esrc  = (const int*)  d_in[1];
    const int*   edst  = (const int*)  d_in[2];
    const float* evals = (const float*)d_in[3];
    const float* W     = (const float*)d_in[4];
    const float* bias  = (const float*)d_in[5];
    float*       out   = (float*)d_out;

    cudaFuncSetAttribute(gemm_hmma_kernel,
                         cudaFuncAttributeMaxDynamicSharedMemorySize, SM_BYTES);

    // fork a non-blocking side stream into the capture graph for the GEMM
    // branch (independent of the CSR build until spmm).
    cudaStream_t s2;
    cudaEvent_t evFork, evJoin;
    cudaStreamCreateWithFlags(&s2, cudaStreamNonBlocking);
    cudaEventCreateWithFlags(&evFork, cudaEventDisableTiming);
    cudaEventCreateWithFlags(&evJoin, cudaEventDisableTiming);

    cudaEventRecord(evFork, 0);
    cudaStreamWaitEvent(s2, evFork, 0);

    // branch A (side stream): W transpose + HMMA GEMM
    wt_kernel<<<(IN_F * OUT_F + 255) / 256, 256, 0, s2>>>(W);
    gemm_hmma_kernel<<<GEMM_TILES, 256, SM_BYTES, s2>>>(x, bias);

    // branch B (main stream): CSR-by-dst build
    zero_deg_kernel<<<(N_NODES + 1023) / 1024, 1024>>>();
    hist_kernel<<<(N_EDGES / 4 + 255) / 256, 256>>>(edst);
    scan1_kernel<<<(N_NODES + 1023) / 1024, 1024>>>();
    scan23_kernel<<<(N_NODES + 1023) / 1024, 1024>>>();
    scatter_kernel<<<(N_EDGES / 4 + 255) / 256, 256>>>(esrc, edst, evals);

    // join, then SpMM
    cudaEventRecord(evJoin, s2);
    cudaStreamWaitEvent(0, evJoin, 0);
    spmm_csr_kernel<<<(N_NODES * 16 + 255) / 256, 256>>>(out);
}